// round 15
// baseline (speedup 1.0000x reference)
#include <cuda_runtime.h>
#include <cuda_bf16.h>
#include <cstdint>

// DistMult edge scoring:
//   out[r, e] = sigmoid( sum_d h[src[r,e], d] * W[r, d] * h[dst[r,e], d] )
// h [100000,128] f32, W [6,128] f32, src/dst [6,200000] int32, out [6,200000] f32.
//
// R15: clean L1-bypass A/B. R14's asm-volatile LDCG wrapper pinned load
// scheduling and inflated regs 32->40 (occ 68%) — confounded. This round
// uses the __ldcg() intrinsic (ulonglong2 overload): same LDG.E.128.CG,
// but ptxas keeps its normal hoisting/batching and 32-reg allocation.
// Body otherwise byte-identical to the R11 champion (GRID_X=2500, ITERS=5,
// 16 lanes/edge, packed f32x2, indices via smem int2).

#define N_HID 128
#define E_PER_REL 200000
#define N_REL 6
#define BLOCK 256
#define EDGES_PER_BLOCK 16      // 256 threads / 16 lanes per edge
#define GRID_X 2500             // 2500 * 16 * 5 == 200000 exactly
#define ITERS 5
#define STRIDE (GRID_X * EDGES_PER_BLOCK)   // 40000
#define ROW_U2 (N_HID / 4)      // 32 ulonglong2 per 128-float row

__device__ __forceinline__ unsigned long long f32x2_mul(unsigned long long a,
                                                        unsigned long long b) {
    unsigned long long r;
    asm("mul.rn.f32x2 %0, %1, %2;" : "=l"(r) : "l"(a), "l"(b));
    return r;
}
__device__ __forceinline__ unsigned long long f32x2_fma(unsigned long long a,
                                                        unsigned long long b,
                                                        unsigned long long c) {
    unsigned long long r;
    asm("fma.rn.f32x2 %0, %1, %2, %3;" : "=l"(r) : "l"(a), "l"(b), "l"(c));
    return r;
}

__global__ __launch_bounds__(BLOCK, 6)
void distmult_kernel(const ulonglong2* __restrict__ h8,   // row = 32 x ulonglong2
                     const ulonglong2* __restrict__ W8,
                     const int* __restrict__ src_idx,
                     const int* __restrict__ dst_idx,
                     float* __restrict__ out) {
    __shared__ int2 SD[ITERS * EDGES_PER_BLOCK];   // packed (s,d), 640 B

    const int rel   = blockIdx.y;
    const int tid   = threadIdx.x;
    const int sub   = tid & 15;    // lane within 16-lane edge group
    const int group = tid >> 4;    // edge slot within block: 0..15

    const int* __restrict__ srcR = src_idx + rel * E_PER_REL;
    const int* __restrict__ dstR = dst_idx + rel * E_PER_REL;
    float* __restrict__ outR = out + rel * E_PER_REL;

    // W row in registers: lane sub owns ulonglong2 chunks {sub, sub+16} of 32.
    const ulonglong2 w0 = W8[rel * ROW_U2 + sub];
    const ulonglong2 w1 = W8[rel * ROW_U2 + sub + 16];

    // Prologue: preload all phase (s,d) pairs, coalesced.
    if (tid < ITERS * EDGES_PER_BLOCK) {
        const int i = tid >> 4;          // phase
        const int g = tid & 15;          // group slot
        const int e = blockIdx.x * EDGES_PER_BLOCK + i * STRIDE + g;
        SD[tid] = make_int2(__ldg(srcR + e), __ldg(dstR + e));
    }
    __syncthreads();

    const int e0 = blockIdx.x * EDGES_PER_BLOCK + group;

    #pragma unroll
    for (int i = 0; i < ITERS; i++) {
        const int2 sd = SD[i * EDGES_PER_BLOCK + group];   // one LDS.64, broadcast

        const ulonglong2* __restrict__ hs = h8 + (long long)sd.x * ROW_U2;
        const ulonglong2* __restrict__ hd = h8 + (long long)sd.y * ROW_U2;

        // 4 independent LDG.128.CG per thread (intrinsic: scheduler-friendly),
        // front-batched, L1-bypass.
        ulonglong2 a0 = __ldcg(hs + sub);
        ulonglong2 a1 = __ldcg(hs + sub + 16);
        ulonglong2 b0 = __ldcg(hd + sub);
        ulonglong2 b1 = __ldcg(hd + sub + 16);

        // Packed math: 8 f32x2 ops cover this thread's 8 dims.
        unsigned long long acc2;
        acc2 = f32x2_mul(f32x2_mul(a0.x, b0.x), w0.x);
        acc2 = f32x2_fma(f32x2_mul(a0.y, b0.y), w0.y, acc2);
        acc2 = f32x2_fma(f32x2_mul(a1.x, b1.x), w1.x, acc2);
        acc2 = f32x2_fma(f32x2_mul(a1.y, b1.y), w1.y, acc2);

        // Fold the two packed halves.
        float lo = __uint_as_float((unsigned)(acc2 & 0xFFFFFFFFull));
        float hi = __uint_as_float((unsigned)(acc2 >> 32));
        float acc = lo + hi;

        // Reduce across the 16-lane group.
        acc += __shfl_xor_sync(0xFFFFFFFFu, acc, 8);
        acc += __shfl_xor_sync(0xFFFFFFFFu, acc, 4);
        acc += __shfl_xor_sync(0xFFFFFFFFu, acc, 2);
        acc += __shfl_xor_sync(0xFFFFFFFFu, acc, 1);

        if (sub == 0)
            outR[e0 + i * STRIDE] = 1.0f / (1.0f + __expf(-acc));
    }
}

extern "C" void kernel_launch(void* const* d_in, const int* in_sizes, int n_in,
                              void* d_out, int out_size) {
    const ulonglong2* h8 = (const ulonglong2*)d_in[0];
    const ulonglong2* W8 = (const ulonglong2*)d_in[1];
    const int* src = (const int*)d_in[2];
    const int* dst = (const int*)d_in[3];
    float* out = (float*)d_out;

    dim3 grid(GRID_X, N_REL);
    distmult_kernel<<<grid, BLOCK>>>(h8, W8, src, dst, out);
}

// round 16
// speedup vs baseline: 1.0088x; 1.0088x over previous
#include <cuda_runtime.h>
#include <cuda_bf16.h>
#include <cstdint>

// DistMult edge scoring:
//   out[r, e] = sigmoid( sum_d h[src[r,e], d] * W[r, d] * h[dst[r,e], d] )
// h [100000,128] f32, W [6,128] f32, src/dst [6,200000] int32, out [6,200000] f32.
//
// R16: R11 champion (GRID_X=2500, ITERS=5, 16 lanes/edge, packed f32x2,
// regs=32, occ=91% — warm-L2 regime sits at the LTS cap) + paired output
// store: lane 16's result is shuffled to lane 0 and the warp's two
// consecutive edge scores go out as ONE aligned STG.64. Halves store
// wavefronts/sectors and drops one predicated sigmoid path per warp.
// (fp16 h compression analyzed and rejected: predicted rel_err ~1.4e-3
// exceeds the 1e-3 threshold.)

#define N_HID 128
#define E_PER_REL 200000
#define N_REL 6
#define BLOCK 256
#define EDGES_PER_BLOCK 16      // 256 threads / 16 lanes per edge
#define GRID_X 2500             // 2500 * 16 * 5 == 200000 exactly
#define ITERS 5
#define STRIDE (GRID_X * EDGES_PER_BLOCK)   // 40000
#define ROW_U2 (N_HID / 4)      // 32 ulonglong2 per 128-float row

__device__ __forceinline__ unsigned long long f32x2_mul(unsigned long long a,
                                                        unsigned long long b) {
    unsigned long long r;
    asm("mul.rn.f32x2 %0, %1, %2;" : "=l"(r) : "l"(a), "l"(b));
    return r;
}
__device__ __forceinline__ unsigned long long f32x2_fma(unsigned long long a,
                                                        unsigned long long b,
                                                        unsigned long long c) {
    unsigned long long r;
    asm("fma.rn.f32x2 %0, %1, %2, %3;" : "=l"(r) : "l"(a), "l"(b), "l"(c));
    return r;
}

__global__ __launch_bounds__(BLOCK, 6)
void distmult_kernel(const ulonglong2* __restrict__ h8,   // row = 32 x ulonglong2
                     const ulonglong2* __restrict__ W8,
                     const int* __restrict__ src_idx,
                     const int* __restrict__ dst_idx,
                     float2* __restrict__ out2) {          // out viewed as float2
    __shared__ int2 SD[ITERS * EDGES_PER_BLOCK];   // packed (s,d), 640 B

    const int rel   = blockIdx.y;
    const int tid   = threadIdx.x;
    const int lane  = tid & 31;
    const int sub   = tid & 15;    // lane within 16-lane edge group
    const int group = tid >> 4;    // edge slot within block: 0..15

    const int* __restrict__ srcR = src_idx + rel * E_PER_REL;
    const int* __restrict__ dstR = dst_idx + rel * E_PER_REL;
    // out2 indexed by edge pair: pair p covers edges {2p, 2p+1}.
    float2* __restrict__ outR2 = out2 + rel * (E_PER_REL / 2);

    // W row in registers: lane sub owns ulonglong2 chunks {sub, sub+16} of 32.
    const ulonglong2 w0 = W8[rel * ROW_U2 + sub];
    const ulonglong2 w1 = W8[rel * ROW_U2 + sub + 16];

    // Prologue: preload all phase (s,d) pairs, coalesced.
    if (tid < ITERS * EDGES_PER_BLOCK) {
        const int i = tid >> 4;          // phase
        const int g = tid & 15;          // group slot
        const int e = blockIdx.x * EDGES_PER_BLOCK + i * STRIDE + g;
        SD[tid] = make_int2(__ldg(srcR + e), __ldg(dstR + e));
    }
    __syncthreads();

    const int e0 = blockIdx.x * EDGES_PER_BLOCK + group;   // this group's base edge

    #pragma unroll
    for (int i = 0; i < ITERS; i++) {
        const int2 sd = SD[i * EDGES_PER_BLOCK + group];   // one LDS.64, broadcast

        const ulonglong2* __restrict__ hs = h8 + (long long)sd.x * ROW_U2;
        const ulonglong2* __restrict__ hd = h8 + (long long)sd.y * ROW_U2;

        // 4 independent LDG.128 per thread, front-batched.
        ulonglong2 a0 = hs[sub];
        ulonglong2 a1 = hs[sub + 16];
        ulonglong2 b0 = hd[sub];
        ulonglong2 b1 = hd[sub + 16];

        // Packed math: 8 f32x2 ops cover this thread's 8 dims.
        unsigned long long acc2;
        acc2 = f32x2_mul(f32x2_mul(a0.x, b0.x), w0.x);
        acc2 = f32x2_fma(f32x2_mul(a0.y, b0.y), w0.y, acc2);
        acc2 = f32x2_fma(f32x2_mul(a1.x, b1.x), w1.x, acc2);
        acc2 = f32x2_fma(f32x2_mul(a1.y, b1.y), w1.y, acc2);

        // Fold the two packed halves.
        float lo = __uint_as_float((unsigned)(acc2 & 0xFFFFFFFFull));
        float hi = __uint_as_float((unsigned)(acc2 >> 32));
        float acc = lo + hi;

        // Reduce across the 16-lane group.
        acc += __shfl_xor_sync(0xFFFFFFFFu, acc, 8);
        acc += __shfl_xor_sync(0xFFFFFFFFu, acc, 4);
        acc += __shfl_xor_sync(0xFFFFFFFFu, acc, 2);
        acc += __shfl_xor_sync(0xFFFFFFFFu, acc, 1);

        // Sigmoid on the two result lanes (0 and 16), then pair the warp's
        // two consecutive edge scores into one STG.64 from lane 0.
        float sig = 1.0f / (1.0f + __expf(-acc));
        float partner = __shfl_xor_sync(0xFFFFFFFFu, sig, 16);
        if (lane == 0) {
            // lane 0: sig = edge (group even), partner = edge+1 (group odd)
            const int e_pair = (e0 + i * STRIDE) >> 1;   // e0 even for lane 0
            outR2[e_pair] = make_float2(sig, partner);
        }
    }
}

extern "C" void kernel_launch(void* const* d_in, const int* in_sizes, int n_in,
                              void* d_out, int out_size) {
    const ulonglong2* h8 = (const ulonglong2*)d_in[0];
    const ulonglong2* W8 = (const ulonglong2*)d_in[1];
    const int* src = (const int*)d_in[2];
    const int* dst = (const int*)d_in[3];
    float2* out2 = (float2*)d_out;

    dim3 grid(GRID_X, N_REL);
    distmult_kernel<<<grid, BLOCK>>>(h8, W8, src, dst, out2);
}

// round 17
// speedup vs baseline: 1.0521x; 1.0430x over previous
#include <cuda_runtime.h>
#include <cuda_bf16.h>
#include <cstdint>

// DistMult edge scoring:
//   out[r, e] = sigmoid( sum_d h[src[r,e], d] * W[r, d] * h[dst[r,e], d] )
// h [100000,128] f32, W [6,128] f32, src/dst [6,200000] int32, out [6,200000] f32.
//
// R17: R16 (paired STG.64 output) with __launch_bounds__(256, 8) to FORCE
// the 32-reg allocation. R14/R15/R16 all showed the same failure: any body
// growth drifts regs 32->38..40, dropping 8->6 CTAs (occ 91->67%), masking
// the experiment. R13 proved min-blocks=8 holds 32 regs spill-free on a
// larger body. This finally A/Bs "half the store wavefronts" at champion
// occupancy.

#define N_HID 128
#define E_PER_REL 200000
#define N_REL 6
#define BLOCK 256
#define EDGES_PER_BLOCK 16      // 256 threads / 16 lanes per edge
#define GRID_X 2500             // 2500 * 16 * 5 == 200000 exactly
#define ITERS 5
#define STRIDE (GRID_X * EDGES_PER_BLOCK)   // 40000
#define ROW_U2 (N_HID / 4)      // 32 ulonglong2 per 128-float row

__device__ __forceinline__ unsigned long long f32x2_mul(unsigned long long a,
                                                        unsigned long long b) {
    unsigned long long r;
    asm("mul.rn.f32x2 %0, %1, %2;" : "=l"(r) : "l"(a), "l"(b));
    return r;
}
__device__ __forceinline__ unsigned long long f32x2_fma(unsigned long long a,
                                                        unsigned long long b,
                                                        unsigned long long c) {
    unsigned long long r;
    asm("fma.rn.f32x2 %0, %1, %2, %3;" : "=l"(r) : "l"(a), "l"(b), "l"(c));
    return r;
}

__global__ __launch_bounds__(BLOCK, 8)
void distmult_kernel(const ulonglong2* __restrict__ h8,   // row = 32 x ulonglong2
                     const ulonglong2* __restrict__ W8,
                     const int* __restrict__ src_idx,
                     const int* __restrict__ dst_idx,
                     float2* __restrict__ out2) {          // out viewed as float2
    __shared__ int2 SD[ITERS * EDGES_PER_BLOCK];   // packed (s,d), 640 B

    const int rel   = blockIdx.y;
    const int tid   = threadIdx.x;
    const int lane  = tid & 31;
    const int sub   = tid & 15;    // lane within 16-lane edge group
    const int group = tid >> 4;    // edge slot within block: 0..15

    const int* __restrict__ srcR = src_idx + rel * E_PER_REL;
    const int* __restrict__ dstR = dst_idx + rel * E_PER_REL;
    // out2 indexed by edge pair: pair p covers edges {2p, 2p+1}.
    float2* __restrict__ outR2 = out2 + rel * (E_PER_REL / 2);

    // W row in registers: lane sub owns ulonglong2 chunks {sub, sub+16} of 32.
    const ulonglong2 w0 = W8[rel * ROW_U2 + sub];
    const ulonglong2 w1 = W8[rel * ROW_U2 + sub + 16];

    // Prologue: preload all phase (s,d) pairs, coalesced.
    if (tid < ITERS * EDGES_PER_BLOCK) {
        const int i = tid >> 4;          // phase
        const int g = tid & 15;          // group slot
        const int e = blockIdx.x * EDGES_PER_BLOCK + i * STRIDE + g;
        SD[tid] = make_int2(__ldg(srcR + e), __ldg(dstR + e));
    }
    __syncthreads();

    const int e0 = blockIdx.x * EDGES_PER_BLOCK + group;   // this group's base edge

    #pragma unroll
    for (int i = 0; i < ITERS; i++) {
        const int2 sd = SD[i * EDGES_PER_BLOCK + group];   // one LDS.64, broadcast

        const ulonglong2* __restrict__ hs = h8 + (long long)sd.x * ROW_U2;
        const ulonglong2* __restrict__ hd = h8 + (long long)sd.y * ROW_U2;

        // 4 independent LDG.128 per thread, front-batched.
        ulonglong2 a0 = hs[sub];
        ulonglong2 a1 = hs[sub + 16];
        ulonglong2 b0 = hd[sub];
        ulonglong2 b1 = hd[sub + 16];

        // Packed math: 8 f32x2 ops cover this thread's 8 dims.
        unsigned long long acc2;
        acc2 = f32x2_mul(f32x2_mul(a0.x, b0.x), w0.x);
        acc2 = f32x2_fma(f32x2_mul(a0.y, b0.y), w0.y, acc2);
        acc2 = f32x2_fma(f32x2_mul(a1.x, b1.x), w1.x, acc2);
        acc2 = f32x2_fma(f32x2_mul(a1.y, b1.y), w1.y, acc2);

        // Fold the two packed halves.
        float lo = __uint_as_float((unsigned)(acc2 & 0xFFFFFFFFull));
        float hi = __uint_as_float((unsigned)(acc2 >> 32));
        float acc = lo + hi;

        // Reduce across the 16-lane group.
        acc += __shfl_xor_sync(0xFFFFFFFFu, acc, 8);
        acc += __shfl_xor_sync(0xFFFFFFFFu, acc, 4);
        acc += __shfl_xor_sync(0xFFFFFFFFu, acc, 2);
        acc += __shfl_xor_sync(0xFFFFFFFFu, acc, 1);

        // Sigmoid on the two result lanes (0 and 16), then pair the warp's
        // two consecutive edge scores into one STG.64 from lane 0.
        float sig = 1.0f / (1.0f + __expf(-acc));
        float partner = __shfl_xor_sync(0xFFFFFFFFu, sig, 16);
        if (lane == 0) {
            const int e_pair = (e0 + i * STRIDE) >> 1;   // e0 even for lane 0
            outR2[e_pair] = make_float2(sig, partner);
        }
    }
}

extern "C" void kernel_launch(void* const* d_in, const int* in_sizes, int n_in,
                              void* d_out, int out_size) {
    const ulonglong2* h8 = (const ulonglong2*)d_in[0];
    const ulonglong2* W8 = (const ulonglong2*)d_in[1];
    const int* src = (const int*)d_in[2];
    const int* dst = (const int*)d_in[3];
    float2* out2 = (float2*)d_out;

    dim3 grid(GRID_X, N_REL);
    distmult_kernel<<<grid, BLOCK>>>(h8, W8, src, dst, out2);
}